// round 16
// baseline (speedup 1.0000x reference)
#include <cuda_runtime.h>

#define T_FRAMES 32768
#define N_LM 543
#define NLEN 512
#define NCOLS 122   // 21*2 hand + 40*2 lips
#define NHANDF 42
#define NLIPSF 80
#define FPB 32      // frames per block in k_frame (512 threads, 2 frames per warp)
#define RAWS 128    // padded row stride of g_raw (floats) -> 512B aligned rows
#define NBLK (T_FRAMES / FPB)

// ---- device scratch (static; no allocations; all zero-init at load) ----
__device__ __align__(128) float g_raw[T_FRAMES * RAWS];
__device__ __align__(128) unsigned g_keep32[NBLK];       // 1 bit per frame, LE-packed
__device__ __align__(128) int   g_map[T_FRAMES];
__device__ float g_lsum[NLIPSF];   // zero at entry of every launch (re-zeroed by fused scan)
__device__ int   g_lcnt[NLIPSF];
__device__ float g_lmean[NLIPSF];
__device__ int   g_S;
__device__ __align__(128) float g_sampled[NLEN * NCOLS];
__device__ unsigned g_rowmask[NLEN / 32];   // zeroed by fused scan before k_segment
__device__ int   g_done;                    // zero at entry (reset by last block)

__device__ __forceinline__ bool is_nan(float v) { return v != v; }

// ---- kernel 1: frame transform + keep bits + raw buffer + lips accum + FUSED scan ----
// Each warp processes 2 frames with ALL loads for both frames batched up-front.
__global__ void __launch_bounds__(512, 3) k_frame(const float* __restrict__ frames,
                                                  const int* __restrict__ lips_idx) {
    __shared__ int   s_lidx[40];
    __shared__ float s_lips[FPB][NLIPSF];
    __shared__ int   s_keepw[FPB];
    __shared__ int   s_last;

    int tib  = threadIdx.x;
    int lane = tib & 31;
    int w    = tib >> 5;
    int tA   = blockIdx.x * FPB + w * 2;   // warp handles frames tA, tA+1
    const float NANF = __int_as_float(0x7fc00000);

    if (tib < 40) s_lidx[tib] = lips_idx[tib];
    __syncthreads();

    const float* fb0 = frames + (size_t)tA * (N_LM * 3);
    const float* fb[2] = { fb0, fb0 + N_LM * 3 };
    int li0 = s_lidx[lane];
    int li1 = (lane < 8) ? s_lidx[32 + lane] : 0;

    // ---- batched loads for BOTH frames (all independent) ----
    float lx[2], ly[2], rx[2], ry[2], x0[2], y0[2], x1[2], y1[2];
    #pragma unroll
    for (int f = 0; f < 2; f++) {
        lx[f] = NANF; ly[f] = NANF; rx[f] = NANF; ry[f] = NANF;
        x1[f] = NANF; y1[f] = NANF;
        if (lane < 21) {
            lx[f] = __ldg(fb[f] + (468 + lane) * 3 + 0);
            ly[f] = __ldg(fb[f] + (468 + lane) * 3 + 1);
            rx[f] = __ldg(fb[f] + (522 + lane) * 3 + 0);
            ry[f] = __ldg(fb[f] + (522 + lane) * 3 + 1);
        }
        x0[f] = __ldg(fb[f] + li0 * 3 + 0);
        y0[f] = __ldg(fb[f] + li0 * 3 + 1);
        if (lane < 8) {
            x1[f] = __ldg(fb[f] + li1 * 3 + 0);
            y1[f] = __ldg(fb[f] + li1 * 3 + 1);
        }
    }

    // ---- per-frame transform + keep + stores + stash ----
    #pragma unroll
    for (int f = 0; f < 2; f++) {
        int t = tA + f;
        float a0 = is_nan(lx[f]) ? 0.f : lx[f];
        float a1 = is_nan(ly[f]) ? 0.f : (1.f - ly[f]);
        float b0 = is_nan(rx[f]) ? 0.f : (1.f - rx[f]);
        float b1 = is_nan(ry[f]) ? 0.f : (1.f - ry[f]);
        float h0 = a0 + b0;
        float h1 = a1 + b1;
        int nz = (lane < 21) && ((h0 != 0.f) | (h1 != 0.f));  // non-negative terms
        unsigned bal = __ballot_sync(0xffffffffu, nz);
        int keep = (bal != 0u);
        if (lane == 0) s_keepw[w * 2 + f] = keep;

        float* row = &g_raw[t * RAWS];
        if (keep) {
            if (lane < 21) *(float2*)(row + 2 * lane) = make_float2(h0, h1);
            *(float2*)(row + NHANDF + 2 * lane) = make_float2(x0[f], y0[f]);
            if (lane < 8) *(float2*)(row + NHANDF + 64 + 2 * lane) = make_float2(x1[f], y1[f]);
        }
        s_lips[w * 2 + f][2 * lane + 0] = keep ? x0[f] : NANF;
        s_lips[w * 2 + f][2 * lane + 1] = keep ? y0[f] : NANF;
        if (lane < 8) {
            s_lips[w * 2 + f][64 + 2 * lane + 0] = keep ? x1[f] : NANF;
            s_lips[w * 2 + f][64 + 2 * lane + 1] = keep ? y1[f] : NANF;
        }
    }
    __syncthreads();

    if (tib == 0) {
        unsigned m = 0;
        #pragma unroll
        for (int f = 0; f < FPB; f++) m |= (unsigned)s_keepw[f] << f;
        g_keep32[blockIdx.x] = m;
    }

    // 80 threads: reduce FPB frames for one column, single global atomic pair
    if (tib < NLIPSF) {
        float s = 0.f; int c = 0;
        #pragma unroll
        for (int f = 0; f < FPB; f++) {
            float v = s_lips[f][tib];
            if (!is_nan(v)) { s += v; c++; }
        }
        if (c) {
            atomicAdd(&g_lsum[tib], s);
            atomicAdd(&g_lcnt[tib], c);
        }
    }

    // ---- last-block election: bar.sync orders CTA writes, ONE fence publishes them ----
    __syncthreads();
    if (tib == 0) {
        __threadfence();                         // release: CTA's writes -> GPU scope
        int v = atomicAdd(&g_done, 1);
        s_last = (v == NBLK - 1);
        if (s_last) {
            g_done = 0;                          // reset for next graph replay
            __threadfence();                     // acquire side
        }
    }
    __syncthreads();
    if (!s_last) return;

    // ==== FUSED SCAN (last block, 512 threads) ====
    if (tib < NLIPSF) {
        int c = g_lcnt[tib];
        g_lmean[tib] = (c > 0) ? g_lsum[tib] / (float)c : 0.f;
        g_lsum[tib] = 0.f;        // restore zero-at-entry invariant
        g_lcnt[tib] = 0;
    }
    if (tib < NLEN / 32) g_rowmask[tib] = 0u;   // zero row bitmask for k_segment

    // each of 512 threads: 64 frames = 2 keep words
    uint2 kv = *((const uint2*)g_keep32 + tib);
    int cnt = __popc(kv.x) + __popc(kv.y);

    __shared__ int s_wsum[16];
    int inc = cnt;
    #pragma unroll
    for (int off = 1; off < 32; off <<= 1) {
        int n = __shfl_up_sync(0xffffffffu, inc, off);
        if (lane >= off) inc += n;
    }
    if (lane == 31) s_wsum[w] = inc;
    __syncthreads();
    if (tib == 0) {
        int acc = 0;
        #pragma unroll
        for (int i = 0; i < 16; i++) { int tmp = s_wsum[i]; s_wsum[i] = acc; acc += tmp; }
        g_S = acc;
    }
    __syncthreads();

    int pos  = s_wsum[w] + inc - cnt;   // exclusive prefix
    int base = tib * 64;
    unsigned words[2] = { kv.x, kv.y };
    #pragma unroll
    for (int q = 0; q < 2; q++) {
        unsigned b = words[q];
        while (b) {
            int i = __ffs(b) - 1;
            g_map[pos++] = base + q * 32 + i;
            b &= b - 1;
        }
    }
}

// ---- kernel 2: segment means (512 blocks x 1024 thr = 128 cols x 8 slices) ----
__global__ void __launch_bounds__(1024) k_segment() {
    int i = blockIdx.x;
    int S = g_S;
    int lo = 0, hi = 0;
    if (S >= 2) {
        long sm1 = (long)(S - 1);
        lo = (int)(((long)i       * sm1) >> 9);   // floor(i*(S-1)/512)
        hi = (int)(((long)(i + 1) * sm1) >> 9);
    }
    int cnt = hi - lo;   // <= 64

    __shared__ int   s_map[66];
    __shared__ float red[8][128];

    if (threadIdx.x < cnt) s_map[threadIdx.x] = g_map[lo + threadIdx.x];
    __syncthreads();

    int j     = threadIdx.x & 127;
    int slice = threadIdx.x >> 7;   // 0..7

    float sum = 0.f;
    if (j < NCOLS) {
        float fill = (j >= NHANDF) ? g_lmean[j - NHANDF] : 0.f;
        #pragma unroll 4
        for (int s = slice; s < cnt; s += 8) {
            int t = s_map[s];
            float v = g_raw[t * RAWS + j];
            sum += is_nan(v) ? fill : v;
        }
    }
    red[slice][j] = sum;
    __syncthreads();

    float mean = 0.f;
    if (slice == 0) {
        float total = red[0][j] + red[1][j] + red[2][j] + red[3][j]
                    + red[4][j] + red[5][j] + red[6][j] + red[7][j];
        if (j < NCOLS) {
            mean = cnt ? total / (float)cnt : 0.f;
            g_sampled[i * NCOLS + j] = mean;
        }
    }
    __syncthreads();
    if (slice == 0) red[0][j] = mean;
    __syncthreads();
    if (threadIdx.x < 32) {
        float r = red[0][threadIdx.x] + red[0][threadIdx.x + 32]
                + red[0][threadIdx.x + 64] + red[0][threadIdx.x + 96];
        #pragma unroll
        for (int off = 16; off; off >>= 1)
            r += __shfl_xor_sync(0xffffffffu, r, off);
        if (threadIdx.x == 0 && r != 0.f)
            atomicOr(&g_rowmask[i >> 5], 1u << (i & 31));
    }
}

// ---- kernel 3: parallel row copy; each block finds its source row from the bitmask ----
__global__ void k_copy(float* __restrict__ out, int out_size) {
    __shared__ int s_src;
    int r = blockIdx.x;
    if (threadIdx.x == 0) {
        int src = -1, acc = 0;
        #pragma unroll
        for (int q = 0; q < NLEN / 32; q++) {
            unsigned m = g_rowmask[q];
            int p = __popc(m);
            if (src < 0 && acc + p > r) {
                int need = r - acc;
                unsigned mm = m;
                for (int z = 0; z < need; z++) mm &= mm - 1;
                src = q * 32 + (__ffs(mm) - 1);
            }
            acc += p;
        }
        s_src = src;   // -1 if r >= R
    }
    __syncthreads();
    int src = s_src;
    if (src < 0) return;
    int j = threadIdx.x;   // 128 threads, 122 used
    if (j < NCOLS) {
        int k = r * NCOLS + j;
        if (k < out_size)
            out[k] = g_sampled[src * NCOLS + j];
    }
}

extern "C" void kernel_launch(void* const* d_in, const int* in_sizes, int n_in,
                              void* d_out, int out_size) {
    const float* frames   = (const float*)d_in[0];
    const int*   lips_idx = (const int*)d_in[1];
    float*       out      = (float*)d_out;

    k_frame<<<NBLK, 512>>>(frames, lips_idx);
    k_segment<<<NLEN, 1024>>>();
    k_copy<<<NLEN, 128>>>(out, out_size);
}